// round 7
// baseline (speedup 1.0000x reference)
#include <cuda_runtime.h>
#include <cstdint>

#define B_   8
#define T_   316
#define CIN_ 64
#define HF_  128
#define G_   32
#define E_   384

#define N_PATCHES (B_*T_*CIN_*64)
#define N_BT      (B_*T_)

#define PATCH_BLOCKS (N_BT / 2)          // 2 tokens per block
#define FMAP_BLOCKS  (B_ * G_ * 4)       // (batch, grid-row, e-quarter)
#define EQ_          96
#define SMS_         97

#define IMG_STRIDE4  (HF_ * HF_ / 4)     // float4 stride between cin planes

// ---------------------------------------------------------------------------
// Single fused kernel.
//   blocks [0, PATCH_BLOCKS):  2 tokens/block, 128 threads/token, each
//                              thread emits 8 float4s (cin = cin0 + 8k) ->
//                              8-16 independent loads in flight per thread.
//   blocks [PATCH_BLOCKS, +FMAP_BLOCKS): fmap transpose-gather.
// ---------------------------------------------------------------------------
__global__ void __launch_bounds__(256) fused_kernel(
        const float* __restrict__ x_in,
        const float* __restrict__ tokens,
        const int*   __restrict__ metas,
        float* __restrict__ patches,
        float* __restrict__ cx,
        float* __restrict__ cy,
        float* __restrict__ sc,
        float* __restrict__ fmap) {

    int tid = threadIdx.x;

    if (blockIdx.x < PATCH_BLOCKS) {
        // --------------------------- patches ---------------------------
        int tok  = blockIdx.x * 2 + (tid >> 7);   // warps 0-3 / 4-7 split
        int ltid = tid & 127;
        int b    = tok / T_;

        const int* m = metas + (size_t)tok * 5;
        int r = m[0], c = m[1], p = m[3];

        if (ltid == 0) {
            int span = m[2];
            float hs = 0.5f * (float)span;
            cx[tok] = (float)c + hs;
            cy[tok] = (float)r + hs;
            sc[tok] = (p == 16) ? 1.0f : ((p == 8) ? 2.0f : 0.0f);
        }

        // decode (invariant in k): half = bit0, i = bits1-3, cin0 = bits4-6
        int half = ltid & 1;
        int i    = (ltid >> 1) & 7;
        int cin0 = ltid >> 4;            // 0..7 ; cin = cin0 + 8k

        const float4* img4 = (const float4*)x_in +
                             ((size_t)b * CIN_ + cin0) * IMG_STRIDE4;
        float4* dst = ((float4*)patches) + (size_t)tok * 1024 + ltid;

        if (p == 16) {
            // pure 8x8 crop at (r*4, c*4)
            int off = (r * 4 + i) * 32 + c + half;   // float4 units
            float4 v[8];
            #pragma unroll
            for (int k = 0; k < 8; k++)
                v[k] = __ldcs(img4 + (size_t)k * 8 * IMG_STRIDE4 + off);
            #pragma unroll
            for (int k = 0; k < 8; k++)
                __stcs(dst + k * 128, v[k]);
        } else if (p > 0) {
            int pf = p >> 1; if (pf < 1) pf = 1;     // <= 4 here
            float pff   = (float)pf;
            float scale = pff * 0.125f;
            float hi    = pff - 1.0f;

            float rel_i = fminf(fmaxf(((float)i + 0.5f) * scale - 0.5f, 0.0f), hi);
            float i0f = floorf(rel_i);
            float wy  = rel_i - i0f;
            float i1f = fminf(i0f + 1.0f, hi);
            int y0off = (r * 4 + (int)i0f) * 32 + c;
            int y1off = (r * 4 + (int)i1f) * 32 + c;

            int   j0[4], j1[4];
            float wx[4];
            #pragma unroll
            for (int jj = 0; jj < 4; jj++) {
                float j = (float)(half * 4 + jj);
                float rel_j = fminf(fmaxf((j + 0.5f) * scale - 0.5f, 0.0f), hi);
                float j0f = floorf(rel_j);
                wx[jj] = rel_j - j0f;
                j0[jj] = (int)j0f;
                int t1 = j0[jj] + 1; if (t1 > (int)hi) t1 = (int)hi;
                j1[jj] = t1;
            }

            float4 t0[8], t1[8];
            #pragma unroll
            for (int k = 0; k < 8; k++) {
                const float4* ik = img4 + (size_t)k * 8 * IMG_STRIDE4;
                t0[k] = __ldcs(ik + y0off);
                t1[k] = __ldcs(ik + y1off);
            }
            #pragma unroll
            for (int k = 0; k < 8; k++) {
                float rb[4];
                rb[0] = t0[k].x + (t1[k].x - t0[k].x) * wy;
                rb[1] = t0[k].y + (t1[k].y - t0[k].y) * wy;
                rb[2] = t0[k].z + (t1[k].z - t0[k].z) * wy;
                rb[3] = t0[k].w + (t1[k].w - t0[k].w) * wy;
                float4 o;
                o.x = rb[j0[0]] + (rb[j1[0]] - rb[j0[0]]) * wx[0];
                o.y = rb[j0[1]] + (rb[j1[1]] - rb[j0[1]]) * wx[1];
                o.z = rb[j0[2]] + (rb[j1[2]] - rb[j0[2]]) * wx[2];
                o.w = rb[j0[3]] + (rb[j1[3]] - rb[j0[3]]) * wx[3];
                __stcs(dst + k * 128, o);
            }
        } else {
            float4 z = make_float4(0.f, 0.f, 0.f, 0.f);
            #pragma unroll
            for (int k = 0; k < 8; k++) __stcs(dst + k * 128, z);
        }
        return;
    }

    // ----------------------------- fmap -----------------------------
    __shared__ float sm[32 * SMS_];
    __shared__ int   s_own[32];

    int fb  = blockIdx.x - PATCH_BLOCKS;
    int q   = fb & 3;
    int row = (fb >> 2) & 31;
    int b   = fb >> 7;
    int lane = tid & 31;
    int w    = tid >> 5;

    // owners for this grid row, from metas (coverage is exact, no races)
    for (int t = tid; t < T_; t += 256) {
        const int* m = metas + (size_t)(b * T_ + t) * 5;
        int r = m[0], c = m[1], span = m[2], p = m[3];
        int di = row - r;
        if (p > 0 && di >= 0 && di < span) {
            for (int dc = 0; dc < span; dc++) {
                int col = c + dc;
                if (col >= 0 && col < G_) s_own[col] = t;
            }
        }
    }
    __syncthreads();

    int e0 = q * EQ_;
    #pragma unroll
    for (int cc = 0; cc < 4; cc++) {
        int cell = w * 4 + cc;
        const float* src = tokens + ((size_t)(b * T_ + s_own[cell])) * E_ + e0;
        #pragma unroll
        for (int it = 0; it < 3; it++) {
            int e = it * 32 + lane;
            sm[cell * SMS_ + e] = __ldg(&src[e]);
        }
    }
    __syncthreads();

    float* dstb = fmap + ((size_t)(b * E_ + e0) + w * 12) * (G_ * G_)
                       + row * 32 + lane;
    #pragma unroll
    for (int k = 0; k < 12; k++)
        __stcs(&dstb[(size_t)k * (G_ * G_)], sm[lane * SMS_ + w * 12 + k]);
}

// ---------------------------------------------------------------------------
extern "C" void kernel_launch(void* const* d_in, const int* in_sizes, int n_in,
                              void* d_out, int out_size) {
    const float* x_in   = (const float*)d_in[0];
    const float* tokens = (const float*)d_in[1];
    const int*   metas  = (const int*)d_in[2];

    float* out     = (float*)d_out;
    float* patches = out;
    float* cx      = out + (size_t)N_PATCHES;
    float* cy      = cx + N_BT;
    float* sc      = cy + N_BT;
    float* fmap    = sc + N_BT;

    fused_kernel<<<PATCH_BLOCKS + FMAP_BLOCKS, 256>>>(
        x_in, tokens, metas, patches, cx, cy, sc, fmap);
}